// round 14
// baseline (speedup 1.0000x reference)
#include <cuda_runtime.h>
#include <cuda_bf16.h>
#include <cstdint>

// ---------------- problem constants ----------------
#define BATCH   8
#define C2DIM   128
#define C3DIM   256
#define HDIM    28
#define WDIM    28
#define H3      14
#define W3      14
#define CDIM    384
#define NPATCH  6272
#define MBANK   30000
#define MBANK_PAD 30720             // 3 splits * 20 tiles * 512 rows

// ---------------- tiling ----------------
#define MSPLIT   3
#define TILE_M   64                 // patches per CTA
#define TILE_N   512                // bank rows per CTA tile (16 warps * 32)
#define NTILES   98                 // NPATCH / TILE_M
#define BTILES   20                 // bank tiles per split (20*512 = 10240)

#define ASTRIDE  392                // bf16 elems per A row (384 + 8 pad)
#define ABYTES   (TILE_M * ASTRIDE * 2)     // 50176
#define BROWB    144                // bytes per B row (64 bf16 + 8 pad)
#define NSTAGE   2
#define WARPSTG  (32 * BROWB)       // 4608: one warp-stage (32 rows x 64 cols)
#define WARPB    (NSTAGE * WARPSTG) // 9216 per warp
#define REDOFF   (ABYTES + 16 * WARPB)      // 197632
#define SM_TOTAL (REDOFF + 16 * TILE_M * 4) // 201728

#define NTHREADS 512
#define TILEBYTES ((size_t)TILE_N * CDIM * 2)   // gmem bytes per bank tile row-block

// prep: patch blocks FIRST (long pole), then bank blocks (2 rows per warp)
#define PREP_PAT_BLOCKS  (NPATCH / 8)           // 784
#define PREP_BANK_BLOCKS (MBANK_PAD / 16)       // 1920
#define PREP_BLOCKS      (PREP_PAT_BLOCKS + PREP_BANK_BLOCKS)

// ---------------- scratch ----------------
__device__ __align__(16) __nv_bfloat16 g_pat_bf[(size_t)NPATCH * CDIM];
__device__ __align__(16) __nv_bfloat16 g_bank_bf[(size_t)MBANK_PAD * CDIM];
__device__ float g_xsq[NPATCH];
__device__ float g_msq[MBANK_PAD];
__device__ float g_part[MSPLIT * NPATCH];
__device__ int   g_cnt[NTILES];     // split-arrival counters (reset each launch)

__device__ __forceinline__ uint32_t s2u(const void* p) {
    uint32_t r;
    asm("{ .reg .u64 t; cvta.to.shared.u64 t, %1; cvt.u32.u64 %0, t; }"
        : "=r"(r) : "l"(p));
    return r;
}

// ============================ fused prep kernel ============================
__global__ void prep_kernel(const float* __restrict__ f2,
                            const float* __restrict__ f3,
                            const float* __restrict__ bank) {
    int lane = threadIdx.x & 31;
    if (blockIdx.x < PREP_PAT_BLOCKS) {
        int n = (blockIdx.x * blockDim.x + threadIdx.x) >> 5;
        int b = n / (HDIM * WDIM);
        int hw = n - b * (HDIM * WDIM);
        int h = hw / WDIM;
        int w = hw - h * WDIM;

        float sh = h * 0.5f - 0.25f;
        float sw = w * 0.5f - 0.25f;
        int h0 = (int)floorf(sh);
        int w0 = (int)floorf(sw);
        float th = sh - (float)h0;
        float tw = sw - (float)w0;
        int h0c = h0 < 0 ? 0 : h0;   int h1c = h0 + 1 > H3 - 1 ? H3 - 1 : h0 + 1;
        int w0c = w0 < 0 ? 0 : w0;   int w1c = w0 + 1 > W3 - 1 ? W3 - 1 : w0 + 1;

        __nv_bfloat16* dst = g_pat_bf + (size_t)n * CDIM;
        float sumsq = 0.f;
        #pragma unroll
        for (int j = 0; j < 12; ++j) {
            int c = lane + j * 32;
            float val;
            if (c < C2DIM) {
                val = f2[(((size_t)b * C2DIM + c) * HDIM + h) * WDIM + w];
            } else {
                int c3 = c - C2DIM;
                const float* base = f3 + ((size_t)b * C3DIM + c3) * (H3 * W3);
                float v00 = base[h0c * W3 + w0c];
                float v01 = base[h0c * W3 + w1c];
                float v10 = base[h1c * W3 + w0c];
                float v11 = base[h1c * W3 + w1c];
                val = (1.f - th) * ((1.f - tw) * v00 + tw * v01)
                    +        th  * ((1.f - tw) * v10 + tw * v11);
            }
            __nv_bfloat16 bv = __float2bfloat16(val);
            dst[c] = bv;
            float f = __bfloat162float(bv);
            sumsq += f * f;
        }
        #pragma unroll
        for (int off = 16; off; off >>= 1)
            sumsq += __shfl_xor_sync(0xffffffffu, sumsq, off);
        if (lane == 0) g_xsq[n] = sumsq;
    } else {
        int wrp = ((blockIdx.x - PREP_PAT_BLOCKS) * blockDim.x + threadIdx.x) >> 5;
        int row0 = wrp * 2;
        uint2* dst0 = (uint2*)(g_bank_bf + (size_t)row0 * CDIM);
        uint2* dst1 = (uint2*)(g_bank_bf + (size_t)(row0 + 1) * CDIM);
        if (row0 >= MBANK) {
            #pragma unroll
            for (int j = 0; j < 3; ++j) {
                dst0[j * 32 + lane] = make_uint2(0u, 0u);
                dst1[j * 32 + lane] = make_uint2(0u, 0u);
            }
            if (lane == 0) {
                g_msq[row0]     = __int_as_float(0x7f800000);
                g_msq[row0 + 1] = __int_as_float(0x7f800000);
            }
            return;
        }
        const float4* src0 = (const float4*)(bank + (size_t)row0 * CDIM);
        const float4* src1 = (const float4*)(bank + (size_t)(row0 + 1) * CDIM);
        float4 a0 = src0[lane], a1 = src0[32 + lane], a2 = src0[64 + lane];
        float4 b0 = src1[lane], b1 = src1[32 + lane], b2 = src1[64 + lane];
        float s0 = 0.f, s1 = 0.f;
        #pragma unroll
        for (int j = 0; j < 3; ++j) {
            float4 va = (j == 0) ? a0 : (j == 1) ? a1 : a2;
            float4 vb = (j == 0) ? b0 : (j == 1) ? b1 : b2;
            __nv_bfloat162 alo = __float22bfloat162_rn(make_float2(va.x, va.y));
            __nv_bfloat162 ahi = __float22bfloat162_rn(make_float2(va.z, va.w));
            __nv_bfloat162 blo = __float22bfloat162_rn(make_float2(vb.x, vb.y));
            __nv_bfloat162 bhi = __float22bfloat162_rn(make_float2(vb.z, vb.w));
            dst0[j * 32 + lane] = make_uint2(*(uint32_t*)&alo, *(uint32_t*)&ahi);
            dst1[j * 32 + lane] = make_uint2(*(uint32_t*)&blo, *(uint32_t*)&bhi);
            float f0 = __bfloat162float(alo.x), f1 = __bfloat162float(alo.y);
            float f2v = __bfloat162float(ahi.x), f3v = __bfloat162float(ahi.y);
            s0 += f0 * f0 + f1 * f1 + f2v * f2v + f3v * f3v;
            float g0 = __bfloat162float(blo.x), g1 = __bfloat162float(blo.y);
            float g2 = __bfloat162float(bhi.x), g3 = __bfloat162float(bhi.y);
            s1 += g0 * g0 + g1 * g1 + g2 * g2 + g3 * g3;
        }
        #pragma unroll
        for (int off = 16; off; off >>= 1) {
            s0 += __shfl_xor_sync(0xffffffffu, s0, off);
            s1 += __shfl_xor_sync(0xffffffffu, s1, off);
        }
        if (lane == 0) {
            g_msq[row0]     = s0;
            g_msq[row0 + 1] = s1;
        }
    }
}

// ============================ main GEMM+min kernel ============================
// 512 threads, 16 warps in 1(m) x 16(n); warp tile 64x32, mma.m16n8k16 bf16.
// Each warp owns a PRIVATE 32-row B slice with a 2-stage cp.async ring -> NO
// barriers in the main loop; warps free-run. Stage-reuse safe: the cp.async
// for chunk j+2 issues after the last MMA of chunk j, whose operands gate on
// the last LDSM of that stage.
__global__ void __launch_bounds__(NTHREADS, 1) nn_kernel(float* __restrict__ out) {
    extern __shared__ __align__(1024) char smem[];
    char* Asm = smem;
    const int tid  = threadIdx.x;
    const int lane = tid & 31;
    const int wid  = tid >> 5;      // 0..15 = n-slice owner
    const int n0   = blockIdx.x * TILE_M;
    const int split = blockIdx.y;
    const int mbase = split * (BTILES * TILE_N);

    const uint32_t aSm = s2u(smem);
    const uint32_t bSm = aSm + ABYTES + (uint32_t)wid * WARPB;   // warp region

    // ---- warp chunk loader: 32 rows x 64 k-cols bf16 = 4KB, 1 warp ----
    const int lr = lane >> 3, lqq = lane & 7;   // 8 lanes cover one 128B row
    auto load_at = [&](const char* src0, uint32_t dbase) {
        #pragma unroll
        for (int i = 0; i < 8; ++i) {
            int r = lr + i * 4;
            uint32_t d = dbase + r * BROWB + lqq * 16;
            const char* s = src0 + (size_t)r * (CDIM * 2) + lqq * 16;
            asm volatile("cp.async.cg.shared.global [%0], [%1], 16;"
                         :: "r"(d), "l"(s));
        }
        asm volatile("cp.async.commit_group;");
    };

    // ---- A tile (64 x 384 bf16) via cp.async, folded into group 0 ----
    #pragma unroll
    for (int i = 0; i < 6; ++i) {
        int e = i * NTHREADS + tid;
        int r = e / 48, q = e - r * 48;
        uint32_t d = aSm + r * (ASTRIDE * 2) + q * 16;
        const char* s = (const char*)(g_pat_bf + (size_t)(n0 + r) * CDIM + q * 8);
        asm volatile("cp.async.cg.shared.global [%0], [%1], 16;"
                     :: "r"(d), "l"(s));
    }

    // warp's gmem base for tile 0
    const char* tileSrc = (const char*)(g_bank_bf +
                          (size_t)(mbase + wid * 32) * CDIM);

    load_at(tileSrc + 0 * 128, bSm + 0 * WARPSTG);   // group0 = A + chunk0
    load_at(tileSrc + 1 * 128, bSm + 1 * WARPSTG);   // group1 = chunk1
    asm volatile("cp.async.wait_group 1;");           // A + chunk0 resident
    __syncthreads();                                  // A visible block-wide

    // per-lane ldmatrix base addresses
    const uint32_t aBase = aSm +
        (((lane & 15)) * ASTRIDE + (lane >> 4) * 8) * 2;
    const int lq = lane >> 3;
    const int bn = (lane & 7) + ((lq >> 1) << 3);    // local row 0..15
    const int bk = (lq & 1) << 3;
    const uint32_t bBase = bSm + bn * BROWB + bk * 2;

    float rowmin[4][2];
    #pragma unroll
    for (int i = 0; i < 4; ++i) {
        rowmin[i][0] = __int_as_float(0x7f800000);
        rowmin[i][1] = __int_as_float(0x7f800000);
    }

    for (int t = 0; t < BTILES; ++t) {
        float acc[4][4][4];
        #pragma unroll
        for (int mt = 0; mt < 4; ++mt)
            #pragma unroll
            for (int nt = 0; nt < 4; ++nt)
                #pragma unroll
                for (int e = 0; e < 4; ++e) acc[mt][nt][e] = 0.f;

        const bool more = (t + 1) < BTILES;
        const char* nextSrc = tileSrc + TILEBYTES;
        float ms[4][2];

        #pragma unroll
        for (int j = 0; j < 6; ++j) {
            asm volatile("cp.async.wait_group 1;");   // own chunk j resident
            if (j == 5) {   // prefetch msq for the fold (hidden by final MMAs)
                const int cb = mbase + t * TILE_N + wid * 32 + (lane & 3) * 2;
                #pragma unroll
                for (int nt = 0; nt < 4; ++nt) {
                    ms[nt][0] = __ldg(&g_msq[cb + nt * 8]);
                    ms[nt][1] = __ldg(&g_msq[cb + nt * 8 + 1]);
                }
            }

            const uint32_t bBuf = bBase + (uint32_t)((j % 2) * WARPSTG);
            #pragma unroll
            for (int s = 0; s < 4; ++s) {
                // B frags: 2 x4-ldmatrix -> 4 n8-tiles x {b0,b1}
                uint32_t b[4][2];
                #pragma unroll
                for (int np = 0; np < 2; ++np) {
                    uint32_t r0, r1, r2, r3;
                    uint32_t ad = bBuf + np * (16 * BROWB) + s * 32;
                    asm volatile(
                        "ldmatrix.sync.aligned.m8n8.x4.shared.b16 "
                        "{%0,%1,%2,%3}, [%4];"
                        : "=r"(r0), "=r"(r1), "=r"(r2), "=r"(r3) : "r"(ad));
                    b[2 * np][0] = r0; b[2 * np][1] = r1;
                    b[2 * np + 1][0] = r2; b[2 * np + 1][1] = r3;
                }
                // A frags: 4 x4-ldmatrix -> 4 m16-tiles x {a0..a3}
                uint32_t a[4][4];
                #pragma unroll
                for (int mt = 0; mt < 4; ++mt) {
                    uint32_t ad = aBase + mt * (16 * ASTRIDE * 2)
                                + (j * 64 + s * 16) * 2;
                    asm volatile(
                        "ldmatrix.sync.aligned.m8n8.x4.shared.b16 "
                        "{%0,%1,%2,%3}, [%4];"
                        : "=r"(a[mt][0]), "=r"(a[mt][1]),
                          "=r"(a[mt][2]), "=r"(a[mt][3]) : "r"(ad));
                }
                #pragma unroll
                for (int mt = 0; mt < 4; ++mt)
                    #pragma unroll
                    for (int nt = 0; nt < 4; ++nt) {
                        asm volatile(
                            "mma.sync.aligned.m16n8k16.row.col.f32.bf16.bf16.f32 "
                            "{%0,%1,%2,%3}, {%4,%5,%6,%7}, {%8,%9}, {%0,%1,%2,%3};"
                            : "+f"(acc[mt][nt][0]), "+f"(acc[mt][nt][1]),
                              "+f"(acc[mt][nt][2]), "+f"(acc[mt][nt][3])
                            : "r"(a[mt][0]), "r"(a[mt][1]),
                              "r"(a[mt][2]), "r"(a[mt][3]),
                              "r"(b[nt][0]), "r"(b[nt][1]));
                    }
            }

            // issue load of chunk j+2 into stage (j%2) — all LDSM reads of this
            // stage completed (MMA operand dependencies), so reuse is safe.
            if (j < 4) {
                load_at(tileSrc + (j + 2) * 128,
                        bSm + (uint32_t)((j % 2) * WARPSTG));
            } else if (more) {
                load_at(nextSrc + (j - 4) * 128,
                        bSm + (uint32_t)((j % 2) * WARPSTG));
            } else {
                asm volatile("cp.async.commit_group;");  // keep group count
            }
        }
        tileSrc = nextSrc;

        // ---- fold tile into persistent row-min regs (msq already in regs) ----
        #pragma unroll
        for (int nt = 0; nt < 4; ++nt) {
            float m0 = ms[nt][0];
            float m1 = ms[nt][1];
            #pragma unroll
            for (int mt = 0; mt < 4; ++mt) {
                float v0 = fmaf(-2.f, acc[mt][nt][0], m0);
                float v1 = fmaf(-2.f, acc[mt][nt][1], m1);
                float v2 = fmaf(-2.f, acc[mt][nt][2], m0);
                float v3 = fmaf(-2.f, acc[mt][nt][3], m1);
                rowmin[mt][0] = fminf(rowmin[mt][0], fminf(v0, v1));
                rowmin[mt][1] = fminf(rowmin[mt][1], fminf(v2, v3));
            }
        }
    }

    // ---- final reduction: lanes sharing rows, then across the 16 warps ----
    #pragma unroll
    for (int mt = 0; mt < 4; ++mt)
        #pragma unroll
        for (int h = 0; h < 2; ++h) {
            float v = rowmin[mt][h];
            v = fminf(v, __shfl_xor_sync(0xffffffffu, v, 1));
            v = fminf(v, __shfl_xor_sync(0xffffffffu, v, 2));
            rowmin[mt][h] = v;
        }
    asm volatile("cp.async.wait_group 0;");
    float* red = (float*)(smem + REDOFF);   // [16 warps][64 rows], private pad
    if ((lane & 3) == 0) {
        #pragma unroll
        for (int mt = 0; mt < 4; ++mt)
            #pragma unroll
            for (int h = 0; h < 2; ++h) {
                int row = mt * 16 + (lane >> 2) + h * 8;
                red[wid * TILE_M + row] = rowmin[mt][h];
            }
    }
    __syncthreads();
    if (tid < TILE_M) {
        float v = red[tid];
        #pragma unroll
        for (int wq = 1; wq < 16; ++wq)
            v = fminf(v, red[wq * TILE_M + tid]);
        g_part[split * NPATCH + n0 + tid] = v;
    }

    // ---- fused finalize: last arriving split-CTA writes out[] ----
    __shared__ int s_last;
    __threadfence();            // publish g_part before the arrival atomic
    __syncthreads();            // order tid<64 stores before tid0 atomic
    if (tid == 0) {
        int old = atomicAdd(&g_cnt[blockIdx.x], 1);
        s_last = (old == MSPLIT - 1) ? 1 : 0;
    }
    __syncthreads();
    if (s_last) {
        if (tid == 0) g_cnt[blockIdx.x] = 0;   // reset for next launch/replay
        if (tid < TILE_M) {
            int n = n0 + tid;
            float m = fminf(g_part[n],
                      fminf(g_part[NPATCH + n], g_part[2 * NPATCH + n]));
            float d2 = fmaxf(g_xsq[n] + m, 1e-12f);
            float v = sqrtf(d2);
            out[n] = v;
            // per-image max (warp-segmented, then one atomic per segment)
            int b = n / (HDIM * WDIM);
            float mv = v;
            #pragma unroll
            for (int off = 16; off; off >>= 1) {
                float o  = __shfl_xor_sync(0xffffffffu, mv, off);
                int   ob = __shfl_xor_sync(0xffffffffu, b,  off);
                if (ob == b) mv = fmaxf(mv, o);
            }
            int prev_b = __shfl_up_sync(0xffffffffu, b, 1);
            if (lane == 0 || prev_b != b)
                atomicMax((int*)&out[NPATCH + b], __float_as_int(mv));
        }
    }
}

// ============================ launch ============================
extern "C" void kernel_launch(void* const* d_in, const int* in_sizes, int n_in,
                              void* d_out, int out_size) {
    const float* f2   = (const float*)d_in[0];
    const float* f3   = (const float*)d_in[1];
    const float* bank = (const float*)d_in[2];
    float* out = (float*)d_out;

    cudaFuncSetAttribute(nn_kernel,
                         cudaFuncAttributeMaxDynamicSharedMemorySize, SM_TOTAL);

    prep_kernel<<<PREP_BLOCKS, 256>>>(f2, f3, bank);

    dim3 grid(NTILES, MSPLIT);
    nn_kernel<<<grid, NTHREADS, SM_TOTAL>>>(out);
}

// round 15
// speedup vs baseline: 1.0136x; 1.0136x over previous
#include <cuda_runtime.h>
#include <cuda_bf16.h>
#include <cstdint>

// ---------------- problem constants ----------------
#define BATCH   8
#define C2DIM   128
#define C3DIM   256
#define HDIM    28
#define WDIM    28
#define H3      14
#define W3      14
#define CDIM    384
#define NPATCH  6272
#define MBANK   30000
#define MBANK_PAD 30720             // 3 splits * 40 tiles * 256 rows

// ---------------- tiling ----------------
#define MSPLIT   3
#define TILE_M   128                // patches per CTA
#define TILE_N   256                // bank rows per CTA tile
#define NTILES   49                 // NPATCH / TILE_M
#define BTILES   40                 // bank tiles per split (40*256 = 10240)

#define ASTRIDE  392                // bf16 elems per A row (384 + 8 pad)
#define ABYTES   (128 * ASTRIDE * 2)    // 100352
#define BROWB    144                // bytes per B row (64 bf16 + 8 pad)
#define NSTAGE   3
#define PAIRSTG  (32 * BROWB)       // 4608 bytes: one pair-stage
#define PAIRB    (NSTAGE * PAIRSTG) // 13824 per pair
#define SM_TOTAL (ABYTES + 8 * PAIRB)   // 210944

#define NTHREADS 512
#define TILEBYTES ((size_t)TILE_N * CDIM * 2)

// prep: bank blocks FIRST (long pole), then 224 smem-staged embed blocks
#define PREP_BANK_BLOCKS (MBANK_PAD / 16)       // 1920 (8 warps, 2 rows/warp)
#define PREP_PAT_BLOCKS  (BATCH * HDIM)         // 224 (block per (b,h))
#define PREP_BLOCKS      (PREP_BANK_BLOCKS + PREP_PAT_BLOCKS)

// ---------------- scratch ----------------
__device__ __align__(16) __nv_bfloat16 g_pat_bf[(size_t)NPATCH * CDIM];
__device__ __align__(16) __nv_bfloat16 g_bank_bf[(size_t)MBANK_PAD * CDIM];
__device__ float g_xsq[NPATCH];
__device__ float g_msq[MBANK_PAD];
__device__ float g_part[MSPLIT * NPATCH];
__device__ int   g_cnt[NTILES];     // split-arrival counters (reset each launch)

__device__ __forceinline__ uint32_t s2u(const void* p) {
    uint32_t r;
    asm("{ .reg .u64 t; cvta.to.shared.u64 t, %1; cvt.u32.u64 %0, t; }"
        : "=r"(r) : "l"(p));
    return r;
}

// ============================ fused prep kernel ============================
// blocks [0, PREP_BANK_BLOCKS): bank fp32->bf16 + msq (warp per 2 rows)
// blocks [PREP_BANK_BLOCKS, ..): smem-staged embed for one (b,h) row
__global__ void prep_kernel(const float* __restrict__ f2,
                            const float* __restrict__ f3,
                            const float* __restrict__ bank) {
    int tid  = threadIdx.x;
    int lane = tid & 31;
    if (blockIdx.x < PREP_BANK_BLOCKS) {
        int wrp = (blockIdx.x * blockDim.x + tid) >> 5;
        int row0 = wrp * 2;
        uint2* dst0 = (uint2*)(g_bank_bf + (size_t)row0 * CDIM);
        uint2* dst1 = (uint2*)(g_bank_bf + (size_t)(row0 + 1) * CDIM);
        if (row0 >= MBANK) {
            #pragma unroll
            for (int j = 0; j < 3; ++j) {
                dst0[j * 32 + lane] = make_uint2(0u, 0u);
                dst1[j * 32 + lane] = make_uint2(0u, 0u);
            }
            if (lane == 0) {
                g_msq[row0]     = __int_as_float(0x7f800000);
                g_msq[row0 + 1] = __int_as_float(0x7f800000);
            }
            return;
        }
        const float4* src0 = (const float4*)(bank + (size_t)row0 * CDIM);
        const float4* src1 = (const float4*)(bank + (size_t)(row0 + 1) * CDIM);
        float4 a0 = src0[lane], a1 = src0[32 + lane], a2 = src0[64 + lane];
        float4 b0 = src1[lane], b1 = src1[32 + lane], b2 = src1[64 + lane];
        float s0 = 0.f, s1 = 0.f;
        #pragma unroll
        for (int j = 0; j < 3; ++j) {
            float4 va = (j == 0) ? a0 : (j == 1) ? a1 : a2;
            float4 vb = (j == 0) ? b0 : (j == 1) ? b1 : b2;
            __nv_bfloat162 alo = __float22bfloat162_rn(make_float2(va.x, va.y));
            __nv_bfloat162 ahi = __float22bfloat162_rn(make_float2(va.z, va.w));
            __nv_bfloat162 blo = __float22bfloat162_rn(make_float2(vb.x, vb.y));
            __nv_bfloat162 bhi = __float22bfloat162_rn(make_float2(vb.z, vb.w));
            dst0[j * 32 + lane] = make_uint2(*(uint32_t*)&alo, *(uint32_t*)&ahi);
            dst1[j * 32 + lane] = make_uint2(*(uint32_t*)&blo, *(uint32_t*)&bhi);
            float f0 = __bfloat162float(alo.x), f1 = __bfloat162float(alo.y);
            float f2v = __bfloat162float(ahi.x), f3v = __bfloat162float(ahi.y);
            s0 += f0 * f0 + f1 * f1 + f2v * f2v + f3v * f3v;
            float g0 = __bfloat162float(blo.x), g1 = __bfloat162float(blo.y);
            float g2 = __bfloat162float(bhi.x), g3 = __bfloat162float(bhi.y);
            s1 += g0 * g0 + g1 * g1 + g2 * g2 + g3 * g3;
        }
        #pragma unroll
        for (int off = 16; off; off >>= 1) {
            s0 += __shfl_xor_sync(0xffffffffu, s0, off);
            s1 += __shfl_xor_sync(0xffffffffu, s1, off);
        }
        if (lane == 0) {
            g_msq[row0]     = s0;
            g_msq[row0 + 1] = s1;
        }
    } else {
        // ---- smem-staged embed: block per (b,h), 256 threads ----
        __shared__ float f2s[C2DIM * 29];            // [c][w] stride 29
        __shared__ float f3s[2][C3DIM * 15];         // [r][c][w] stride 15
        int bx = blockIdx.x - PREP_BANK_BLOCKS;
        int b = bx / HDIM;
        int h = bx - b * HDIM;

        float sh = h * 0.5f - 0.25f;
        int h0 = (int)floorf(sh);
        float th = sh - (float)h0;
        int h0c = h0 < 0 ? 0 : h0;
        int h1c = h0 + 1 > H3 - 1 ? H3 - 1 : h0 + 1;

        // coalesced loads: f2 row-block (128c x 28w)
        for (int fi = tid; fi < C2DIM * WDIM; fi += 256) {
            int c = fi / WDIM, w = fi - c * WDIM;
            f2s[c * 29 + w] = f2[(((size_t)b * C2DIM + c) * HDIM + h) * WDIM + w];
        }
        // f3: two h-rows (256c x 14w each)
        for (int fi = tid; fi < 2 * C3DIM * W3; fi += 256) {
            int r = fi / (C3DIM * W3);
            int rem = fi - r * (C3DIM * W3);
            int c = rem / W3, w = rem - c * W3;
            int hr = r ? h1c : h0c;
            f3s[r][c * 15 + w] =
                f3[(((size_t)b * C3DIM + c) * H3 + hr) * W3 + w];
        }
        __syncthreads();

        int w = tid >> 3;        // 0..31 (only <28 used)
        int sub = tid & 7;
        if (w < WDIM) {
            float sw = w * 0.5f - 0.25f;
            int w0 = (int)floorf(sw);
            float tw = sw - (float)w0;
            int w0c = w0 < 0 ? 0 : w0;
            int w1c = w0 + 1 > W3 - 1 ? W3 - 1 : w0 + 1;

            int n = b * (HDIM * WDIM) + h * WDIM + w;
            uint2* orow = (uint2*)(g_pat_bf + (size_t)n * CDIM);
            float ssq = 0.f;
            #pragma unroll
            for (int i = 0; i < 12; ++i) {
                int c0 = i * 32 + sub * 4;   // 4 consecutive channels
                float v[4];
                #pragma unroll
                for (int cc = 0; cc < 4; ++cc) {
                    int c = c0 + cc;
                    if (i < 4) {             // c < 128 always here
                        v[cc] = f2s[c * 29 + w];
                    } else {
                        int c3 = c - C2DIM;
                        float v00 = f3s[0][c3 * 15 + w0c];
                        float v01 = f3s[0][c3 * 15 + w1c];
                        float v10 = f3s[1][c3 * 15 + w0c];
                        float v11 = f3s[1][c3 * 15 + w1c];
                        v[cc] = (1.f - th) * ((1.f - tw) * v00 + tw * v01)
                              +        th  * ((1.f - tw) * v10 + tw * v11);
                    }
                }
                __nv_bfloat16 q0 = __float2bfloat16(v[0]);
                __nv_bfloat16 q1 = __float2bfloat16(v[1]);
                __nv_bfloat16 q2 = __float2bfloat16(v[2]);
                __nv_bfloat16 q3 = __float2bfloat16(v[3]);
                uint32_t lo = ((uint32_t)*(uint16_t*)&q1 << 16) | *(uint16_t*)&q0;
                uint32_t hi = ((uint32_t)*(uint16_t*)&q3 << 16) | *(uint16_t*)&q2;
                orow[i * 8 + sub] = make_uint2(lo, hi);
                float f0 = __bfloat162float(q0), f1 = __bfloat162float(q1);
                float f2v = __bfloat162float(q2), f3v = __bfloat162float(q3);
                ssq += f0 * f0 + f1 * f1 + f2v * f2v + f3v * f3v;
            }
            // deterministic reduction over the 8 sub-lanes
            ssq += __shfl_down_sync(0xffffffffu, ssq, 4);
            ssq += __shfl_down_sync(0xffffffffu, ssq, 2);
            ssq += __shfl_down_sync(0xffffffffu, ssq, 1);
            if (sub == 0) g_xsq[n] = ssq;
        }
    }
}

// ============================ main GEMM+min kernel (R13, frozen) ============
__global__ void __launch_bounds__(NTHREADS, 1) nn_kernel(float* __restrict__ out) {
    extern __shared__ __align__(1024) char smem[];
    char* Asm = smem;
    const int tid  = threadIdx.x;
    const int lane = tid & 31;
    const int wid  = tid >> 5;
    const int wm   = wid >> 3;      // 0..1
    const int wn   = wid & 7;       // 0..7
    const int n0   = blockIdx.x * TILE_M;
    const int split = blockIdx.y;
    const int mbase = split * (BTILES * TILE_N);

    const uint32_t aSm = s2u(smem);
    const uint32_t bSm = aSm + ABYTES + (uint32_t)wn * PAIRB;   // pair region

    const int l64 = wm * 32 + lane;
    const int lr = l64 >> 3, lqq = l64 & 7;
    auto load_at = [&](const char* src0, uint32_t dbase) {
        #pragma unroll
        for (int i = 0; i < 4; ++i) {
            int r = lr + i * 8;
            uint32_t d = dbase + r * BROWB + lqq * 16;
            const char* s = src0 + (size_t)r * (CDIM * 2) + lqq * 16;
            asm volatile("cp.async.cg.shared.global [%0], [%1], 16;"
                         :: "r"(d), "l"(s));
        }
        asm volatile("cp.async.commit_group;");
    };

    // A tile (128 x 384 bf16) via cp.async, folded into group 0
    #pragma unroll
    for (int i = 0; i < 12; ++i) {
        int e = i * NTHREADS + tid;
        int r = e / 48, q = e - r * 48;
        uint32_t d = aSm + r * (ASTRIDE * 2) + q * 16;
        const char* s = (const char*)(g_pat_bf + (size_t)(n0 + r) * CDIM + q * 8);
        asm volatile("cp.async.cg.shared.global [%0], [%1], 16;"
                     :: "r"(d), "l"(s));
    }

    const char* tileSrc = (const char*)(g_bank_bf +
                          (size_t)(mbase + wn * 32) * CDIM);

    load_at(tileSrc + 0 * 128, bSm + 0 * PAIRSTG);
    load_at(tileSrc + 1 * 128, bSm + 1 * PAIRSTG);
    asm volatile("cp.async.wait_group 1;");
    __syncthreads();

    const uint32_t aBase = aSm +
        ((wm * 64 + (lane & 15)) * ASTRIDE + (lane >> 4) * 8) * 2;
    const int lq = lane >> 3;
    const int bn = (lane & 7) + ((lq >> 1) << 3);
    const int bk = (lq & 1) << 3;
    const uint32_t bBase = bSm + bn * BROWB + bk * 2;

    float rowmin[4][2];
    #pragma unroll
    for (int i = 0; i < 4; ++i) {
        rowmin[i][0] = __int_as_float(0x7f800000);
        rowmin[i][1] = __int_as_float(0x7f800000);
    }

    const int barid = wn + 1;
    for (int t = 0; t < BTILES; ++t) {
        float acc[4][4][4];
        #pragma unroll
        for (int mt = 0; mt < 4; ++mt)
            #pragma unroll
            for (int nt = 0; nt < 4; ++nt)
                #pragma unroll
                for (int e = 0; e < 4; ++e) acc[mt][nt][e] = 0.f;

        const bool more = (t + 1) < BTILES;
        const char* nextSrc = tileSrc + TILEBYTES;
        float ms[4][2];

        #pragma unroll
        for (int j = 0; j < 6; ++j) {
            asm volatile("cp.async.wait_group 1;");
            asm volatile("bar.sync %0, 64;" :: "r"(barid) : "memory");
            if (j < 4) {
                load_at(tileSrc + (j + 2) * 128,
                        bSm + (uint32_t)(((j + 2) % 3) * PAIRSTG));
            } else if (more) {
                load_at(nextSrc + (j - 4) * 128,
                        bSm + (uint32_t)(((j + 2) % 3) * PAIRSTG));
            } else {
                asm volatile("cp.async.commit_group;");
            }
            if (j == 5) {
                const int cb = mbase + t * TILE_N + wn * 32 + (lane & 3) * 2;
                #pragma unroll
                for (int nt = 0; nt < 4; ++nt) {
                    ms[nt][0] = __ldg(&g_msq[cb + nt * 8]);
                    ms[nt][1] = __ldg(&g_msq[cb + nt * 8 + 1]);
                }
            }

            const uint32_t bBuf = bBase + (uint32_t)((j % 3) * PAIRSTG);
            #pragma unroll
            for (int s = 0; s < 4; ++s) {
                uint32_t b[4][2];
                #pragma unroll
                for (int np = 0; np < 2; ++np) {
                    uint32_t r0, r1, r2, r3;
                    uint32_t ad = bBuf + np * (16 * BROWB) + s * 32;
                    asm volatile(
                        "ldmatrix.sync.aligned.m8n8.x4.shared.b16 "
                        "{%0,%1,%2,%3}, [%4];"
                        : "=r"(r0), "=r"(r1), "=r"(r2), "=r"(r3) : "r"(ad));
                    b[2 * np][0] = r0; b[2 * np][1] = r1;
                    b[2 * np + 1][0] = r2; b[2 * np + 1][1] = r3;
                }
                uint32_t a[4][4];
                #pragma unroll
                for (int mt = 0; mt < 4; ++mt) {
                    uint32_t ad = aBase + mt * (16 * ASTRIDE * 2)
                                + (j * 64 + s * 16) * 2;
                    asm volatile(
                        "ldmatrix.sync.aligned.m8n8.x4.shared.b16 "
                        "{%0,%1,%2,%3}, [%4];"
                        : "=r"(a[mt][0]), "=r"(a[mt][1]),
                          "=r"(a[mt][2]), "=r"(a[mt][3]) : "r"(ad));
                }
                #pragma unroll
                for (int mt = 0; mt < 4; ++mt)
                    #pragma unroll
                    for (int nt = 0; nt < 4; ++nt) {
                        asm volatile(
                            "mma.sync.aligned.m16n8k16.row.col.f32.bf16.bf16.f32 "
                            "{%0,%1,%2,%3}, {%4,%5,%6,%7}, {%8,%9}, {%0,%1,%2,%3};"
                            : "+f"(acc[mt][nt][0]), "+f"(acc[mt][nt][1]),
                              "+f"(acc[mt][nt][2]), "+f"(acc[mt][nt][3])
                            : "r"(a[mt][0]), "r"(a[mt][1]),
                              "r"(a[mt][2]), "r"(a[mt][3]),
                              "r"(b[nt][0]), "r"(b[nt][1]));
                    }
            }
        }
        tileSrc = nextSrc;

        #pragma unroll
        for (int nt = 0; nt < 4; ++nt) {
            float m0 = ms[nt][0];
            float m1 = ms[nt][1];
            #pragma unroll
            for (int mt = 0; mt < 4; ++mt) {
                float v0 = fmaf(-2.f, acc[mt][nt][0], m0);
                float v1 = fmaf(-2.f, acc[mt][nt][1], m1);
                float v2 = fmaf(-2.f, acc[mt][nt][2], m0);
                float v3 = fmaf(-2.f, acc[mt][nt][3], m1);
                rowmin[mt][0] = fminf(rowmin[mt][0], fminf(v0, v1));
                rowmin[mt][1] = fminf(rowmin[mt][1], fminf(v2, v3));
            }
        }
    }

    #pragma unroll
    for (int mt = 0; mt < 4; ++mt)
        #pragma unroll
        for (int h = 0; h < 2; ++h) {
            float v = rowmin[mt][h];
            v = fminf(v, __shfl_xor_sync(0xffffffffu, v, 1));
            v = fminf(v, __shfl_xor_sync(0xffffffffu, v, 2));
            rowmin[mt][h] = v;
        }
    asm volatile("cp.async.wait_group 0;");
    __syncthreads();
    float* red = (float*)Asm;
    if ((lane & 3) == 0) {
        #pragma unroll
        for (int mt = 0; mt < 4; ++mt)
            #pragma unroll
            for (int h = 0; h < 2; ++h) {
                int row = wm * 64 + mt * 16 + (lane >> 2) + h * 8;
                red[wn * 128 + row] = rowmin[mt][h];
            }
    }
    __syncthreads();
    if (tid < 128) {
        float v = red[tid];
        #pragma unroll
        for (int wq = 1; wq < 8; ++wq)
            v = fminf(v, red[wq * 128 + tid]);
        g_part[split * NPATCH + n0 + tid] = v;
    }

    // fused finalize: last arriving split-CTA writes out[]
    __shared__ int s_last;
    __threadfence();
    __syncthreads();
    if (tid == 0) {
        int old = atomicAdd(&g_cnt[blockIdx.x], 1);
        s_last = (old == MSPLIT - 1) ? 1 : 0;
    }
    __syncthreads();
    if (s_last) {
        if (tid == 0) g_cnt[blockIdx.x] = 0;
        if (tid < 128) {
            int n = n0 + tid;
            float m = fminf(g_part[n],
                      fminf(g_part[NPATCH + n], g_part[2 * NPATCH + n]));
            float d2 = fmaxf(g_xsq[n] + m, 1e-12f);
            float v = sqrtf(d2);
            out[n] = v;
            int b = n / (HDIM * WDIM);
            float mv = v;
            #pragma unroll
            for (int off = 16; off; off >>= 1) {
                float o  = __shfl_xor_sync(0xffffffffu, mv, off);
                int   ob = __shfl_xor_sync(0xffffffffu, b,  off);
                if (ob == b) mv = fmaxf(mv, o);
            }
            int prev_b = __shfl_up_sync(0xffffffffu, b, 1);
            if (lane == 0 || prev_b != b)
                atomicMax((int*)&out[NPATCH + b], __float_as_int(mv));
        }
    }
}

// ============================ launch ============================
extern "C" void kernel_launch(void* const* d_in, const int* in_sizes, int n_in,
                              void* d_out, int out_size) {
    const float* f2   = (const float*)d_in[0];
    const float* f3   = (const float*)d_in[1];
    const float* bank = (const float*)d_in[2];
    float* out = (float*)d_out;

    cudaFuncSetAttribute(nn_kernel,
                         cudaFuncAttributeMaxDynamicSharedMemorySize, SM_TOTAL);

    prep_kernel<<<PREP_BLOCKS, 256>>>(f2, f3, bank);

    dim3 grid(NTILES, MSPLIT);
    nn_kernel<<<grid, NTHREADS, SM_TOTAL>>>(out);
}

// round 16
// speedup vs baseline: 1.0398x; 1.0258x over previous
#include <cuda_runtime.h>
#include <cuda_bf16.h>
#include <cstdint>

// ---------------- problem constants ----------------
#define BATCH   8
#define C2DIM   128
#define C3DIM   256
#define HDIM    28
#define WDIM    28
#define H3      14
#define W3      14
#define CDIM    384
#define NPATCH  6272
#define MBANK   30000
#define MBANK_PAD 30720             // 3 splits * 40 tiles * 256 rows

// ---------------- tiling ----------------
#define MSPLIT   3
#define TILE_M   128                // patches per CTA
#define TILE_N   256                // bank rows per CTA tile
#define NTILES   49                 // NPATCH / TILE_M
#define BTILES   40                 // bank tiles per split (40*256 = 10240)

#define ASTRIDE  392                // bf16 elems per A row (384 + 8 pad)
#define ABYTES   (128 * ASTRIDE * 2)    // 100352
#define BROWB    144                // bytes per B row (64 bf16 + 8 pad)
#define NSTAGE   3
#define PAIRSTG  (32 * BROWB)       // 4608 bytes: one pair-stage
#define PAIRB    (NSTAGE * PAIRSTG) // 13824 per pair
#define SM_TOTAL (ABYTES + 8 * PAIRB)   // 210944

#define NTHREADS 512
#define TILEBYTES ((size_t)TILE_N * CDIM * 2)

// prep: embed blocks FIRST (overlap inside the bank stream), bank after
#define PREP_PAT_BLOCKS  (BATCH * HDIM)         // 224 (block per (b,h))
#define PREP_BANK_BLOCKS (MBANK_PAD / 16)       // 1920 (8 warps, 2 rows/warp)
#define PREP_BLOCKS      (PREP_PAT_BLOCKS + PREP_BANK_BLOCKS)

// ---------------- scratch ----------------
__device__ __align__(16) __nv_bfloat16 g_pat_bf[(size_t)NPATCH * CDIM];
__device__ __align__(16) __nv_bfloat16 g_bank_bf[(size_t)MBANK_PAD * CDIM];
__device__ float g_xsq[NPATCH];
__device__ float g_msq[MBANK_PAD];
__device__ float g_part[MSPLIT * NPATCH];
__device__ int   g_cnt[NTILES];     // split-arrival counters (reset each launch)

__device__ __forceinline__ uint32_t s2u(const void* p) {
    uint32_t r;
    asm("{ .reg .u64 t; cvta.to.shared.u64 t, %1; cvt.u32.u64 %0, t; }"
        : "=r"(r) : "l"(p));
    return r;
}

// ============================ fused prep kernel ============================
// blocks [0, PREP_PAT_BLOCKS): smem-staged embed for one (b,h) row
// blocks [PREP_PAT_BLOCKS, ..): bank fp32->bf16 + msq (warp per 2 rows)
__global__ void prep_kernel(const float* __restrict__ f2,
                            const float* __restrict__ f3,
                            const float* __restrict__ bank) {
    int tid  = threadIdx.x;
    int lane = tid & 31;
    if (blockIdx.x >= PREP_PAT_BLOCKS) {
        int wrp = ((blockIdx.x - PREP_PAT_BLOCKS) * blockDim.x + tid) >> 5;
        int row0 = wrp * 2;
        uint2* dst0 = (uint2*)(g_bank_bf + (size_t)row0 * CDIM);
        uint2* dst1 = (uint2*)(g_bank_bf + (size_t)(row0 + 1) * CDIM);
        if (row0 >= MBANK) {
            #pragma unroll
            for (int j = 0; j < 3; ++j) {
                dst0[j * 32 + lane] = make_uint2(0u, 0u);
                dst1[j * 32 + lane] = make_uint2(0u, 0u);
            }
            if (lane == 0) {
                g_msq[row0]     = __int_as_float(0x7f800000);
                g_msq[row0 + 1] = __int_as_float(0x7f800000);
            }
            return;
        }
        const float4* src0 = (const float4*)(bank + (size_t)row0 * CDIM);
        const float4* src1 = (const float4*)(bank + (size_t)(row0 + 1) * CDIM);
        float4 a0 = src0[lane], a1 = src0[32 + lane], a2 = src0[64 + lane];
        float4 b0 = src1[lane], b1 = src1[32 + lane], b2 = src1[64 + lane];
        float s0 = 0.f, s1 = 0.f;
        #pragma unroll
        for (int j = 0; j < 3; ++j) {
            float4 va = (j == 0) ? a0 : (j == 1) ? a1 : a2;
            float4 vb = (j == 0) ? b0 : (j == 1) ? b1 : b2;
            __nv_bfloat162 alo = __float22bfloat162_rn(make_float2(va.x, va.y));
            __nv_bfloat162 ahi = __float22bfloat162_rn(make_float2(va.z, va.w));
            __nv_bfloat162 blo = __float22bfloat162_rn(make_float2(vb.x, vb.y));
            __nv_bfloat162 bhi = __float22bfloat162_rn(make_float2(vb.z, vb.w));
            dst0[j * 32 + lane] = make_uint2(*(uint32_t*)&alo, *(uint32_t*)&ahi);
            dst1[j * 32 + lane] = make_uint2(*(uint32_t*)&blo, *(uint32_t*)&bhi);
            float f0 = __bfloat162float(alo.x), f1 = __bfloat162float(alo.y);
            float f2v = __bfloat162float(ahi.x), f3v = __bfloat162float(ahi.y);
            s0 += f0 * f0 + f1 * f1 + f2v * f2v + f3v * f3v;
            float g0 = __bfloat162float(blo.x), g1 = __bfloat162float(blo.y);
            float g2 = __bfloat162float(bhi.x), g3 = __bfloat162float(bhi.y);
            s1 += g0 * g0 + g1 * g1 + g2 * g2 + g3 * g3;
        }
        #pragma unroll
        for (int off = 16; off; off >>= 1) {
            s0 += __shfl_xor_sync(0xffffffffu, s0, off);
            s1 += __shfl_xor_sync(0xffffffffu, s1, off);
        }
        if (lane == 0) {
            g_msq[row0]     = s0;
            g_msq[row0 + 1] = s1;
        }
    } else {
        // ---- smem-staged embed: block per (b,h), 256 threads ----
        __shared__ float f2s[C2DIM * 29];            // [c][w] stride 29
        __shared__ float f3s[2][C3DIM * 15];         // [r][c][w] stride 15
        int bx = blockIdx.x;
        int b = bx / HDIM;
        int h = bx - b * HDIM;

        float sh = h * 0.5f - 0.25f;
        int h0 = (int)floorf(sh);
        float th = sh - (float)h0;
        int h0c = h0 < 0 ? 0 : h0;
        int h1c = h0 + 1 > H3 - 1 ? H3 - 1 : h0 + 1;

        // coalesced loads: f2 row-block (128c x 28w)
        for (int fi = tid; fi < C2DIM * WDIM; fi += 256) {
            int c = fi / WDIM, w = fi - c * WDIM;
            f2s[c * 29 + w] = f2[(((size_t)b * C2DIM + c) * HDIM + h) * WDIM + w];
        }
        // f3: two h-rows (256c x 14w each)
        for (int fi = tid; fi < 2 * C3DIM * W3; fi += 256) {
            int r = fi / (C3DIM * W3);
            int rem = fi - r * (C3DIM * W3);
            int c = rem / W3, w = rem - c * W3;
            int hr = r ? h1c : h0c;
            f3s[r][c * 15 + w] =
                f3[(((size_t)b * C3DIM + c) * H3 + hr) * W3 + w];
        }
        __syncthreads();

        int w = tid >> 3;        // 0..31 (only <28 used)
        int sub = tid & 7;
        if (w < WDIM) {
            float sw = w * 0.5f - 0.25f;
            int w0 = (int)floorf(sw);
            float tw = sw - (float)w0;
            int w0c = w0 < 0 ? 0 : w0;
            int w1c = w0 + 1 > W3 - 1 ? W3 - 1 : w0 + 1;

            int n = b * (HDIM * WDIM) + h * WDIM + w;
            uint2* orow = (uint2*)(g_pat_bf + (size_t)n * CDIM);
            float ssq = 0.f;
            #pragma unroll
            for (int i = 0; i < 12; ++i) {
                int c0 = i * 32 + sub * 4;   // 4 consecutive channels
                float v[4];
                #pragma unroll
                for (int cc = 0; cc < 4; ++cc) {
                    int c = c0 + cc;
                    if (i < 4) {             // c < 128 always here
                        v[cc] = f2s[c * 29 + w];
                    } else {
                        int c3 = c - C2DIM;
                        float v00 = f3s[0][c3 * 15 + w0c];
                        float v01 = f3s[0][c3 * 15 + w1c];
                        float v10 = f3s[1][c3 * 15 + w0c];
                        float v11 = f3s[1][c3 * 15 + w1c];
                        v[cc] = (1.f - th) * ((1.f - tw) * v00 + tw * v01)
                              +        th  * ((1.f - tw) * v10 + tw * v11);
                    }
                }
                __nv_bfloat16 q0 = __float2bfloat16(v[0]);
                __nv_bfloat16 q1 = __float2bfloat16(v[1]);
                __nv_bfloat16 q2 = __float2bfloat16(v[2]);
                __nv_bfloat16 q3 = __float2bfloat16(v[3]);
                uint32_t lo = ((uint32_t)*(uint16_t*)&q1 << 16) | *(uint16_t*)&q0;
                uint32_t hi = ((uint32_t)*(uint16_t*)&q3 << 16) | *(uint16_t*)&q2;
                orow[i * 8 + sub] = make_uint2(lo, hi);
                float f0 = __bfloat162float(q0), f1 = __bfloat162float(q1);
                float f2v = __bfloat162float(q2), f3v = __bfloat162float(q3);
                ssq += f0 * f0 + f1 * f1 + f2v * f2v + f3v * f3v;
            }
            // deterministic reduction over the 8 sub-lanes
            ssq += __shfl_down_sync(0xffffffffu, ssq, 4);
            ssq += __shfl_down_sync(0xffffffffu, ssq, 2);
            ssq += __shfl_down_sync(0xffffffffu, ssq, 1);
            if (sub == 0) g_xsq[n] = ssq;
        }
    }
}

// ============================ main GEMM+min kernel (frozen) ============
__global__ void __launch_bounds__(NTHREADS, 1) nn_kernel(float* __restrict__ out) {
    extern __shared__ __align__(1024) char smem[];
    char* Asm = smem;
    const int tid  = threadIdx.x;
    const int lane = tid & 31;
    const int wid  = tid >> 5;
    const int wm   = wid >> 3;      // 0..1
    const int wn   = wid & 7;       // 0..7
    const int n0   = blockIdx.x * TILE_M;
    const int split = blockIdx.y;
    const int mbase = split * (BTILES * TILE_N);

    const uint32_t aSm = s2u(smem);
    const uint32_t bSm = aSm + ABYTES + (uint32_t)wn * PAIRB;   // pair region

    const int l64 = wm * 32 + lane;
    const int lr = l64 >> 3, lqq = l64 & 7;
    auto load_at = [&](const char* src0, uint32_t dbase) {
        #pragma unroll
        for (int i = 0; i < 4; ++i) {
            int r = lr + i * 8;
            uint32_t d = dbase + r * BROWB + lqq * 16;
            const char* s = src0 + (size_t)r * (CDIM * 2) + lqq * 16;
            asm volatile("cp.async.cg.shared.global [%0], [%1], 16;"
                         :: "r"(d), "l"(s));
        }
        asm volatile("cp.async.commit_group;");
    };

    // A tile (128 x 384 bf16) via cp.async, folded into group 0
    #pragma unroll
    for (int i = 0; i < 12; ++i) {
        int e = i * NTHREADS + tid;
        int r = e / 48, q = e - r * 48;
        uint32_t d = aSm + r * (ASTRIDE * 2) + q * 16;
        const char* s = (const char*)(g_pat_bf + (size_t)(n0 + r) * CDIM + q * 8);
        asm volatile("cp.async.cg.shared.global [%0], [%1], 16;"
                     :: "r"(d), "l"(s));
    }

    const char* tileSrc = (const char*)(g_bank_bf +
                          (size_t)(mbase + wn * 32) * CDIM);

    load_at(tileSrc + 0 * 128, bSm + 0 * PAIRSTG);
    load_at(tileSrc + 1 * 128, bSm + 1 * PAIRSTG);
    asm volatile("cp.async.wait_group 1;");
    __syncthreads();

    const uint32_t aBase = aSm +
        ((wm * 64 + (lane & 15)) * ASTRIDE + (lane >> 4) * 8) * 2;
    const int lq = lane >> 3;
    const int bn = (lane & 7) + ((lq >> 1) << 3);
    const int bk = (lq & 1) << 3;
    const uint32_t bBase = bSm + bn * BROWB + bk * 2;

    float rowmin[4][2];
    #pragma unroll
    for (int i = 0; i < 4; ++i) {
        rowmin[i][0] = __int_as_float(0x7f800000);
        rowmin[i][1] = __int_as_float(0x7f800000);
    }

    const int barid = wn + 1;
    for (int t = 0; t < BTILES; ++t) {
        float acc[4][4][4];
        #pragma unroll
        for (int mt = 0; mt < 4; ++mt)
            #pragma unroll
            for (int nt = 0; nt < 4; ++nt)
                #pragma unroll
                for (int e = 0; e < 4; ++e) acc[mt][nt][e] = 0.f;

        const bool more = (t + 1) < BTILES;
        const char* nextSrc = tileSrc + TILEBYTES;
        float ms[4][2];

        #pragma unroll
        for (int j = 0; j < 6; ++j) {
            asm volatile("cp.async.wait_group 1;");
            asm volatile("bar.sync %0, 64;" :: "r"(barid) : "memory");
            if (j < 4) {
                load_at(tileSrc + (j + 2) * 128,
                        bSm + (uint32_t)(((j + 2) % 3) * PAIRSTG));
            } else if (more) {
                load_at(nextSrc + (j - 4) * 128,
                        bSm + (uint32_t)(((j + 2) % 3) * PAIRSTG));
            } else {
                asm volatile("cp.async.commit_group;");
            }
            if (j == 5) {
                const int cb = mbase + t * TILE_N + wn * 32 + (lane & 3) * 2;
                #pragma unroll
                for (int nt = 0; nt < 4; ++nt) {
                    ms[nt][0] = __ldg(&g_msq[cb + nt * 8]);
                    ms[nt][1] = __ldg(&g_msq[cb + nt * 8 + 1]);
                }
            }

            const uint32_t bBuf = bBase + (uint32_t)((j % 3) * PAIRSTG);
            #pragma unroll
            for (int s = 0; s < 4; ++s) {
                uint32_t b[4][2];
                #pragma unroll
                for (int np = 0; np < 2; ++np) {
                    uint32_t r0, r1, r2, r3;
                    uint32_t ad = bBuf + np * (16 * BROWB) + s * 32;
                    asm volatile(
                        "ldmatrix.sync.aligned.m8n8.x4.shared.b16 "
                        "{%0,%1,%2,%3}, [%4];"
                        : "=r"(r0), "=r"(r1), "=r"(r2), "=r"(r3) : "r"(ad));
                    b[2 * np][0] = r0; b[2 * np][1] = r1;
                    b[2 * np + 1][0] = r2; b[2 * np + 1][1] = r3;
                }
                uint32_t a[4][4];
                #pragma unroll
                for (int mt = 0; mt < 4; ++mt) {
                    uint32_t ad = aBase + mt * (16 * ASTRIDE * 2)
                                + (j * 64 + s * 16) * 2;
                    asm volatile(
                        "ldmatrix.sync.aligned.m8n8.x4.shared.b16 "
                        "{%0,%1,%2,%3}, [%4];"
                        : "=r"(a[mt][0]), "=r"(a[mt][1]),
                          "=r"(a[mt][2]), "=r"(a[mt][3]) : "r"(ad));
                }
                #pragma unroll
                for (int mt = 0; mt < 4; ++mt)
                    #pragma unroll
                    for (int nt = 0; nt < 4; ++nt) {
                        asm volatile(
                            "mma.sync.aligned.m16n8k16.row.col.f32.bf16.bf16.f32 "
                            "{%0,%1,%2,%3}, {%4,%5,%6,%7}, {%8,%9}, {%0,%1,%2,%3};"
                            : "+f"(acc[mt][nt][0]), "+f"(acc[mt][nt][1]),
                              "+f"(acc[mt][nt][2]), "+f"(acc[mt][nt][3])
                            : "r"(a[mt][0]), "r"(a[mt][1]),
                              "r"(a[mt][2]), "r"(a[mt][3]),
                              "r"(b[nt][0]), "r"(b[nt][1]));
                    }
            }
        }
        tileSrc = nextSrc;

        #pragma unroll
        for (int nt = 0; nt < 4; ++nt) {
            float m0 = ms[nt][0];
            float m1 = ms[nt][1];
            #pragma unroll
            for (int mt = 0; mt < 4; ++mt) {
                float v0 = fmaf(-2.f, acc[mt][nt][0], m0);
                float v1 = fmaf(-2.f, acc[mt][nt][1], m1);
                float v2 = fmaf(-2.f, acc[mt][nt][2], m0);
                float v3 = fmaf(-2.f, acc[mt][nt][3], m1);
                rowmin[mt][0] = fminf(rowmin[mt][0], fminf(v0, v1));
                rowmin[mt][1] = fminf(rowmin[mt][1], fminf(v2, v3));
            }
        }
    }

    #pragma unroll
    for (int mt = 0; mt < 4; ++mt)
        #pragma unroll
        for (int h = 0; h < 2; ++h) {
            float v = rowmin[mt][h];
            v = fminf(v, __shfl_xor_sync(0xffffffffu, v, 1));
            v = fminf(v, __shfl_xor_sync(0xffffffffu, v, 2));
            rowmin[mt][h] = v;
        }
    asm volatile("cp.async.wait_group 0;");
    __syncthreads();
    float* red = (float*)Asm;
    if ((lane & 3) == 0) {
        #pragma unroll
        for (int mt = 0; mt < 4; ++mt)
            #pragma unroll
            for (int h = 0; h < 2; ++h) {
                int row = wm * 64 + mt * 16 + (lane >> 2) + h * 8;
                red[wn * 128 + row] = rowmin[mt][h];
            }
    }
    __syncthreads();
    if (tid < 128) {
        float v = red[tid];
        #pragma unroll
        for (int wq = 1; wq < 8; ++wq)
            v = fminf(v, red[wq * 128 + tid]);
        g_part[split * NPATCH + n0 + tid] = v;
    }

    // fused finalize: last arriving split-CTA writes out[]
    __shared__ int s_last;
    __threadfence();
    __syncthreads();
    if (tid == 0) {
        int old = atomicAdd(&g_cnt[blockIdx.x], 1);
        s_last = (old == MSPLIT - 1) ? 1 : 0;
    }
    __syncthreads();
    if (s_last) {
        if (tid == 0) g_cnt[blockIdx.x] = 0;
        if (tid < 128) {
            int n = n0 + tid;
            float m = fminf(g_part[n],
                      fminf(g_part[NPATCH + n], g_part[2 * NPATCH + n]));
            float d2 = fmaxf(g_xsq[n] + m, 1e-12f);
            float v = sqrtf(d2);
            out[n] = v;
            int b = n / (HDIM * WDIM);
            float mv = v;
            #pragma unroll
            for (int off = 16; off; off >>= 1) {
                float o  = __shfl_xor_sync(0xffffffffu, mv, off);
                int   ob = __shfl_xor_sync(0xffffffffu, b,  off);
                if (ob == b) mv = fmaxf(mv, o);
            }
            int prev_b = __shfl_up_sync(0xffffffffu, b, 1);
            if (lane == 0 || prev_b != b)
                atomicMax((int*)&out[NPATCH + b], __float_as_int(mv));
        }
    }
}

// ============================ launch ============================
extern "C" void kernel_launch(void* const* d_in, const int* in_sizes, int n_in,
                              void* d_out, int out_size) {
    const float* f2   = (const float*)d_in[0];
    const float* f3   = (const float*)d_in[1];
    const float* bank = (const float*)d_in[2];
    float* out = (float*)d_out;

    cudaFuncSetAttribute(nn_kernel,
                         cudaFuncAttributeMaxDynamicSharedMemorySize, SM_TOTAL);

    prep_kernel<<<PREP_BLOCKS, 256>>>(f2, f3, bank);

    dim3 grid(NTILES, MSPLIT);
    nn_kernel<<<grid, NTHREADS, SM_TOTAL>>>(out);
}

// round 17
// speedup vs baseline: 1.0587x; 1.0182x over previous
#include <cuda_runtime.h>
#include <cuda_bf16.h>
#include <cstdint>

// ---------------- problem constants ----------------
#define BATCH   8
#define C2DIM   128
#define C3DIM   256
#define HDIM    28
#define WDIM    28
#define H3      14
#define W3      14
#define CDIM    384
#define NPATCH  6272
#define MBANK   30000
#define MBANK_PAD 30720             // 3 splits * 40 tiles * 256 rows

// ---------------- tiling ----------------
#define MSPLIT   3
#define TILE_M   128                // patches per CTA
#define TILE_N   256                // bank rows per CTA tile
#define NTILES   49                 // NPATCH / TILE_M
#define BTILES   40                 // bank tiles per split (40*256 = 10240)

#define ASTRIDE  392                // bf16 elems per A row (384 + 8 pad)
#define ABYTES   (128 * ASTRIDE * 2)    // 100352
#define BROWB    144                // bytes per B row (64 bf16 + 8 pad)
#define NSTAGE   3
#define PAIRSTG  (32 * BROWB)       // 4608 bytes: one pair-stage
#define PAIRB    (NSTAGE * PAIRSTG) // 13824 per pair
#define SM_TOTAL (ABYTES + 8 * PAIRB)   // 210944

#define NTHREADS 512
#define TILEBYTES ((size_t)TILE_N * CDIM * 2)

// prep: embed blocks FIRST (overlap inside the bank stream), bank after
#define PREP_PAT_BLOCKS  (BATCH * HDIM)         // 224 (block per (b,h))
#define PREP_BANK_BLOCKS (MBANK_PAD / 16)       // 1920 (8 warps, 2 rows/warp)
#define PREP_BLOCKS      (PREP_PAT_BLOCKS + PREP_BANK_BLOCKS)

// ---------------- scratch ----------------
__device__ __align__(16) __nv_bfloat16 g_pat_bf[(size_t)NPATCH * CDIM];
__device__ __align__(16) __nv_bfloat16 g_bank_bf[(size_t)MBANK_PAD * CDIM];
__device__ float g_xsq[NPATCH];
__device__ float g_msq[MBANK_PAD];
__device__ float g_part[MSPLIT * NPATCH];
__device__ int   g_cnt[NTILES];     // split-arrival counters (reset each launch)

__device__ __forceinline__ uint32_t s2u(const void* p) {
    uint32_t r;
    asm("{ .reg .u64 t; cvta.to.shared.u64 t, %1; cvt.u32.u64 %0, t; }"
        : "=r"(r) : "l"(p));
    return r;
}

// ============================ fused prep kernel ============================
// blocks [0, PREP_PAT_BLOCKS): smem-staged embed for one (b,h) row
// blocks [PREP_PAT_BLOCKS, ..): bank fp32->bf16 + msq (warp per 2 rows)
__global__ void prep_kernel(const float* __restrict__ f2,
                            const float* __restrict__ f3,
                            const float* __restrict__ bank) {
    int tid  = threadIdx.x;
    int lane = tid & 31;
    if (blockIdx.x >= PREP_PAT_BLOCKS) {
        int wrp = ((blockIdx.x - PREP_PAT_BLOCKS) * blockDim.x + tid) >> 5;
        int row0 = wrp * 2;
        uint2* dst0 = (uint2*)(g_bank_bf + (size_t)row0 * CDIM);
        uint2* dst1 = (uint2*)(g_bank_bf + (size_t)(row0 + 1) * CDIM);
        if (row0 >= MBANK) {
            #pragma unroll
            for (int j = 0; j < 3; ++j) {
                dst0[j * 32 + lane] = make_uint2(0u, 0u);
                dst1[j * 32 + lane] = make_uint2(0u, 0u);
            }
            if (lane == 0) {
                g_msq[row0]     = __int_as_float(0x7f800000);
                g_msq[row0 + 1] = __int_as_float(0x7f800000);
            }
            return;
        }
        const float4* src0 = (const float4*)(bank + (size_t)row0 * CDIM);
        const float4* src1 = (const float4*)(bank + (size_t)(row0 + 1) * CDIM);
        float4 a0 = src0[lane], a1 = src0[32 + lane], a2 = src0[64 + lane];
        float4 b0 = src1[lane], b1 = src1[32 + lane], b2 = src1[64 + lane];
        float s0 = 0.f, s1 = 0.f;
        #pragma unroll
        for (int j = 0; j < 3; ++j) {
            float4 va = (j == 0) ? a0 : (j == 1) ? a1 : a2;
            float4 vb = (j == 0) ? b0 : (j == 1) ? b1 : b2;
            __nv_bfloat162 alo = __float22bfloat162_rn(make_float2(va.x, va.y));
            __nv_bfloat162 ahi = __float22bfloat162_rn(make_float2(va.z, va.w));
            __nv_bfloat162 blo = __float22bfloat162_rn(make_float2(vb.x, vb.y));
            __nv_bfloat162 bhi = __float22bfloat162_rn(make_float2(vb.z, vb.w));
            dst0[j * 32 + lane] = make_uint2(*(uint32_t*)&alo, *(uint32_t*)&ahi);
            dst1[j * 32 + lane] = make_uint2(*(uint32_t*)&blo, *(uint32_t*)&bhi);
            float f0 = __bfloat162float(alo.x), f1 = __bfloat162float(alo.y);
            float f2v = __bfloat162float(ahi.x), f3v = __bfloat162float(ahi.y);
            s0 += f0 * f0 + f1 * f1 + f2v * f2v + f3v * f3v;
            float g0 = __bfloat162float(blo.x), g1 = __bfloat162float(blo.y);
            float g2 = __bfloat162float(bhi.x), g3 = __bfloat162float(bhi.y);
            s1 += g0 * g0 + g1 * g1 + g2 * g2 + g3 * g3;
        }
        #pragma unroll
        for (int off = 16; off; off >>= 1) {
            s0 += __shfl_xor_sync(0xffffffffu, s0, off);
            s1 += __shfl_xor_sync(0xffffffffu, s1, off);
        }
        if (lane == 0) {
            g_msq[row0]     = s0;
            g_msq[row0 + 1] = s1;
        }
    } else {
        // ---- smem-staged embed: block per (b,h), 256 threads ----
        __shared__ float f2s[C2DIM * 29];            // [c][w] stride 29
        __shared__ float f3s[2][C3DIM * 15];         // [r][c][w] stride 15
        int bx = blockIdx.x;
        int b = bx / HDIM;
        int h = bx - b * HDIM;

        float sh = h * 0.5f - 0.25f;
        int h0 = (int)floorf(sh);
        float th = sh - (float)h0;
        int h0c = h0 < 0 ? 0 : h0;
        int h1c = h0 + 1 > H3 - 1 ? H3 - 1 : h0 + 1;

        for (int fi = tid; fi < C2DIM * WDIM; fi += 256) {
            int c = fi / WDIM, w = fi - c * WDIM;
            f2s[c * 29 + w] = f2[(((size_t)b * C2DIM + c) * HDIM + h) * WDIM + w];
        }
        for (int fi = tid; fi < 2 * C3DIM * W3; fi += 256) {
            int r = fi / (C3DIM * W3);
            int rem = fi - r * (C3DIM * W3);
            int c = rem / W3, w = rem - c * W3;
            int hr = r ? h1c : h0c;
            f3s[r][c * 15 + w] =
                f3[(((size_t)b * C3DIM + c) * H3 + hr) * W3 + w];
        }
        __syncthreads();

        int w = tid >> 3;        // 0..31 (only <28 used)
        int sub = tid & 7;
        if (w < WDIM) {
            float sw = w * 0.5f - 0.25f;
            int w0 = (int)floorf(sw);
            float tw = sw - (float)w0;
            int w0c = w0 < 0 ? 0 : w0;
            int w1c = w0 + 1 > W3 - 1 ? W3 - 1 : w0 + 1;

            int n = b * (HDIM * WDIM) + h * WDIM + w;
            uint2* orow = (uint2*)(g_pat_bf + (size_t)n * CDIM);
            float ssq = 0.f;
            #pragma unroll
            for (int i = 0; i < 12; ++i) {
                int c0 = i * 32 + sub * 4;
                float v[4];
                #pragma unroll
                for (int cc = 0; cc < 4; ++cc) {
                    int c = c0 + cc;
                    if (i < 4) {
                        v[cc] = f2s[c * 29 + w];
                    } else {
                        int c3 = c - C2DIM;
                        float v00 = f3s[0][c3 * 15 + w0c];
                        float v01 = f3s[0][c3 * 15 + w1c];
                        float v10 = f3s[1][c3 * 15 + w0c];
                        float v11 = f3s[1][c3 * 15 + w1c];
                        v[cc] = (1.f - th) * ((1.f - tw) * v00 + tw * v01)
                              +        th  * ((1.f - tw) * v10 + tw * v11);
                    }
                }
                __nv_bfloat16 q0 = __float2bfloat16(v[0]);
                __nv_bfloat16 q1 = __float2bfloat16(v[1]);
                __nv_bfloat16 q2 = __float2bfloat16(v[2]);
                __nv_bfloat16 q3 = __float2bfloat16(v[3]);
                uint32_t lo = ((uint32_t)*(uint16_t*)&q1 << 16) | *(uint16_t*)&q0;
                uint32_t hi = ((uint32_t)*(uint16_t*)&q3 << 16) | *(uint16_t*)&q2;
                orow[i * 8 + sub] = make_uint2(lo, hi);
                float f0 = __bfloat162float(q0), f1 = __bfloat162float(q1);
                float f2v = __bfloat162float(q2), f3v = __bfloat162float(q3);
                ssq += f0 * f0 + f1 * f1 + f2v * f2v + f3v * f3v;
            }
            ssq += __shfl_down_sync(0xffffffffu, ssq, 4);
            ssq += __shfl_down_sync(0xffffffffu, ssq, 2);
            ssq += __shfl_down_sync(0xffffffffu, ssq, 1);
            if (sub == 0) g_xsq[n] = ssq;
        }
    }
}

// ============================ main GEMM+min kernel ============================
__global__ void __launch_bounds__(NTHREADS, 1) nn_kernel(float* __restrict__ out) {
    extern __shared__ __align__(1024) char smem[];
    char* Asm = smem;
    const int tid  = threadIdx.x;
    const int lane = tid & 31;
    const int wid  = tid >> 5;
    const int wm   = wid >> 3;      // 0..1
    const int wn   = wid & 7;       // 0..7
    const int n0   = blockIdx.x * TILE_M;
    const int split = blockIdx.y;
    const int mbase = split * (BTILES * TILE_N);

    const uint32_t aSm = s2u(smem);
    const uint32_t bSm = aSm + ABYTES + (uint32_t)wn * PAIRB;   // pair region

    const int l64 = wm * 32 + lane;
    const int lr = l64 >> 3, lqq = l64 & 7;
    auto load_at = [&](const char* src0, uint32_t dbase) {
        #pragma unroll
        for (int i = 0; i < 4; ++i) {
            int r = lr + i * 8;
            uint32_t d = dbase + r * BROWB + lqq * 16;
            const char* s = src0 + (size_t)r * (CDIM * 2) + lqq * 16;
            asm volatile("cp.async.cg.shared.global [%0], [%1], 16;"
                         :: "r"(d), "l"(s));
        }
        asm volatile("cp.async.commit_group;");
    };

    // A tile (128 x 384 bf16) via cp.async, folded into group 0
    #pragma unroll
    for (int i = 0; i < 12; ++i) {
        int e = i * NTHREADS + tid;
        int r = e / 48, q = e - r * 48;
        uint32_t d = aSm + r * (ASTRIDE * 2) + q * 16;
        const char* s = (const char*)(g_pat_bf + (size_t)(n0 + r) * CDIM + q * 8);
        asm volatile("cp.async.cg.shared.global [%0], [%1], 16;"
                     :: "r"(d), "l"(s));
    }

    const char* tileSrc = (const char*)(g_bank_bf +
                          (size_t)(mbase + wn * 32) * CDIM);

    load_at(tileSrc + 0 * 128, bSm + 0 * PAIRSTG);
    load_at(tileSrc + 1 * 128, bSm + 1 * PAIRSTG);
    asm volatile("cp.async.wait_group 1;");
    __syncthreads();

    const uint32_t aBase = aSm +
        ((wm * 64 + (lane & 15)) * ASTRIDE + (lane >> 4) * 8) * 2;
    const int lq = lane >> 3;
    const int bn = (lane & 7) + ((lq >> 1) << 3);
    const int bk = (lq & 1) << 3;
    const uint32_t bBase = bSm + bn * BROWB + bk * 2;

    float rowmin[4][2];
    #pragma unroll
    for (int i = 0; i < 4; ++i) {
        rowmin[i][0] = __int_as_float(0x7f800000);
        rowmin[i][1] = __int_as_float(0x7f800000);
    }

    const int barid = wn + 1;
    for (int t = 0; t < BTILES; ++t) {
        float acc[4][4][4];
        #pragma unroll
        for (int mt = 0; mt < 4; ++mt)
            #pragma unroll
            for (int nt = 0; nt < 4; ++nt)
                #pragma unroll
                for (int e = 0; e < 4; ++e) acc[mt][nt][e] = 0.f;

        const bool more = (t + 1) < BTILES;
        const char* nextSrc = tileSrc + TILEBYTES;
        float ms[4][2];

        #pragma unroll
        for (int j = 0; j < 6; ++j) {
            // barrier first (partner-ordering only), own-data wait second:
            // the barrier's arrival skew overlaps the cp.async wait.
            asm volatile("bar.sync %0, 64;" :: "r"(barid) : "memory");
            asm volatile("cp.async.wait_group 1;");
            if (j < 4) {
                load_at(tileSrc + (j + 2) * 128,
                        bSm + (uint32_t)(((j + 2) % 3) * PAIRSTG));
            } else if (more) {
                load_at(nextSrc + (j - 4) * 128,
                        bSm + (uint32_t)(((j + 2) % 3) * PAIRSTG));
            } else {
                asm volatile("cp.async.commit_group;");
            }
            if (j == 4) {   // prefetch msq two barriers before the fold
                const int cb = mbase + t * TILE_N + wn * 32 + (lane & 3) * 2;
                #pragma unroll
                for (int nt = 0; nt < 4; ++nt) {
                    ms[nt][0] = __ldg(&g_msq[cb + nt * 8]);
                    ms[nt][1] = __ldg(&g_msq[cb + nt * 8 + 1]);
                }
            }

            const uint32_t bBuf = bBase + (uint32_t)((j % 3) * PAIRSTG);
            #pragma unroll
            for (int s = 0; s < 4; ++s) {
                uint32_t b[4][2];
                #pragma unroll
                for (int np = 0; np < 2; ++np) {
                    uint32_t r0, r1, r2, r3;
                    uint32_t ad = bBuf + np * (16 * BROWB) + s * 32;
                    asm volatile(
                        "ldmatrix.sync.aligned.m8n8.x4.shared.b16 "
                        "{%0,%1,%2,%3}, [%4];"
                        : "=r"(r0), "=r"(r1), "=r"(r2), "=r"(r3) : "r"(ad));
                    b[2 * np][0] = r0; b[2 * np][1] = r1;
                    b[2 * np + 1][0] = r2; b[2 * np + 1][1] = r3;
                }
                uint32_t a[4][4];
                #pragma unroll
                for (int mt = 0; mt < 4; ++mt) {
                    uint32_t ad = aBase + mt * (16 * ASTRIDE * 2)
                                + (j * 64 + s * 16) * 2;
                    asm volatile(
                        "ldmatrix.sync.aligned.m8n8.x4.shared.b16 "
                        "{%0,%1,%2,%3}, [%4];"
                        : "=r"(a[mt][0]), "=r"(a[mt][1]),
                          "=r"(a[mt][2]), "=r"(a[mt][3]) : "r"(ad));
                }
                #pragma unroll
                for (int mt = 0; mt < 4; ++mt)
                    #pragma unroll
                    for (int nt = 0; nt < 4; ++nt) {
                        asm volatile(
                            "mma.sync.aligned.m16n8k16.row.col.f32.bf16.bf16.f32 "
                            "{%0,%1,%2,%3}, {%4,%5,%6,%7}, {%8,%9}, {%0,%1,%2,%3};"
                            : "+f"(acc[mt][nt][0]), "+f"(acc[mt][nt][1]),
                              "+f"(acc[mt][nt][2]), "+f"(acc[mt][nt][3])
                            : "r"(a[mt][0]), "r"(a[mt][1]),
                              "r"(a[mt][2]), "r"(a[mt][3]),
                              "r"(b[nt][0]), "r"(b[nt][1]));
                    }
            }
        }
        tileSrc = nextSrc;

        #pragma unroll
        for (int nt = 0; nt < 4; ++nt) {
            float m0 = ms[nt][0];
            float m1 = ms[nt][1];
            #pragma unroll
            for (int mt = 0; mt < 4; ++mt) {
                float v0 = fmaf(-2.f, acc[mt][nt][0], m0);
                float v1 = fmaf(-2.f, acc[mt][nt][1], m1);
                float v2 = fmaf(-2.f, acc[mt][nt][2], m0);
                float v3 = fmaf(-2.f, acc[mt][nt][3], m1);
                rowmin[mt][0] = fminf(rowmin[mt][0], fminf(v0, v1));
                rowmin[mt][1] = fminf(rowmin[mt][1], fminf(v2, v3));
            }
        }
    }

    #pragma unroll
    for (int mt = 0; mt < 4; ++mt)
        #pragma unroll
        for (int h = 0; h < 2; ++h) {
            float v = rowmin[mt][h];
            v = fminf(v, __shfl_xor_sync(0xffffffffu, v, 1));
            v = fminf(v, __shfl_xor_sync(0xffffffffu, v, 2));
            rowmin[mt][h] = v;
        }
    asm volatile("cp.async.wait_group 0;");
    __syncthreads();
    float* red = (float*)Asm;
    if ((lane & 3) == 0) {
        #pragma unroll
        for (int mt = 0; mt < 4; ++mt)
            #pragma unroll
            for (int h = 0; h < 2; ++h) {
                int row = wm * 64 + mt * 16 + (lane >> 2) + h * 8;
                red[wn * 128 + row] = rowmin[mt][h];
            }
    }
    __syncthreads();
    if (tid < 128) {
        float v = red[tid];
        #pragma unroll
        for (int wq = 1; wq < 8; ++wq)
            v = fminf(v, red[wq * 128 + tid]);
        g_part[split * NPATCH + n0 + tid] = v;
    }

    // fused finalize: last arriving split-CTA writes out[]
    __shared__ int s_last;
    __threadfence();
    __syncthreads();
    if (tid == 0) {
        int old = atomicAdd(&g_cnt[blockIdx.x], 1);
        s_last = (old == MSPLIT - 1) ? 1 : 0;
    }
    __syncthreads();
    if (s_last) {
        if (tid == 0) g_cnt[blockIdx.x] = 0;
        if (tid < 128) {
            int n = n0 + tid;
            float m = fminf(g_part[n],
                      fminf(g_part[NPATCH + n], g_part[2 * NPATCH + n]));
            float d2 = fmaxf(g_xsq[n] + m, 1e-12f);
            float v = sqrtf(d2);
            out[n] = v;
            int b = n / (HDIM * WDIM);
            float mv = v;
            #pragma unroll
            for (int off = 16; off; off >>= 1) {
                float o  = __shfl_xor_sync(0xffffffffu, mv, off);
                int   ob = __shfl_xor_sync(0xffffffffu, b,  off);
                if (ob == b) mv = fmaxf(mv, o);
            }
            int prev_b = __shfl_up_sync(0xffffffffu, b, 1);
            if (lane == 0 || prev_b != b)
                atomicMax((int*)&out[NPATCH + b], __float_as_int(mv));
        }
    }
}

// ============================ launch ============================
extern "C" void kernel_launch(void* const* d_in, const int* in_sizes, int n_in,
                              void* d_out, int out_size) {
    const float* f2   = (const float*)d_in[0];
    const float* f3   = (const float*)d_in[1];
    const float* bank = (const float*)d_in[2];
    float* out = (float*)d_out;

    cudaFuncSetAttribute(nn_kernel,
                         cudaFuncAttributeMaxDynamicSharedMemorySize, SM_TOTAL);

    prep_kernel<<<PREP_BLOCKS, 256>>>(f2, f3, bank);

    dim3 grid(NTILES, MSPLIT);
    nn_kernel<<<grid, NTHREADS, SM_TOTAL>>>(out);
}